// round 10
// baseline (speedup 1.0000x reference)
#include <cuda_runtime.h>

typedef unsigned long long u64;

// ---------------- scratch (static device globals: allocation-free) ----------------
__device__ __align__(128) float g_k1t[4*8*4096*16];    // [b,h,s,d]
__device__ __align__(128) float g_v1t[4*8*4096*16];
__device__ __align__(128) float g_q1t[4*8*4096*16];
__device__ __align__(128) float g_k0t[4*8*16384*16];
__device__ __align__(128) float g_v0t[4*8*16384*16];
__device__ __align__(128) float g_q0t[4*8*16384*16];
__device__ __align__(128) float g_k2t[4*8*1024*16];
__device__ __align__(128) float g_v2t[4*8*1024*16];
__device__ __align__(128) float g_msg0[4*8*1024*16];       // [b,h,l,d]
__device__ __align__(128) float g_msg1[4*8*1024*4*16];     // [b,h,l,t,d]
__device__ __align__(128) float g_msg2[4*8*4096*4*16];     // [b,h,l,t,d]
__device__ int   g_idx0[4*8*1024*16];          // [b,h,l,16]
__device__ int   g_idx1[4*8*4096*8];           // [b,h,pix,8]

// ---------------- packed f32x2 helpers ----------------
__device__ __forceinline__ u64 pack2(float a, float b) {
    u64 r; asm("mov.b64 %0,{%1,%2};" : "=l"(r) : "f"(a), "f"(b)); return r;
}
__device__ __forceinline__ void unpack2(u64 v, float& a, float& b) {
    asm("mov.b64 {%0,%1},%2;" : "=f"(a), "=f"(b) : "l"(v));
}
__device__ __forceinline__ u64 ffma2(u64 a, u64 b, u64 c) {
    u64 d; asm("fma.rn.f32x2 %0,%1,%2,%3;" : "=l"(d) : "l"(a), "l"(b), "l"(c)); return d;
}
__device__ __forceinline__ u64 mul2(u64 a, u64 b) {
    u64 d; asm("mul.rn.f32x2 %0,%1,%2;" : "=l"(d) : "l"(a), "l"(b)); return d;
}
__device__ __forceinline__ u64 add2(u64 a, u64 b) {
    u64 d; asm("add.rn.f32x2 %0,%1,%2;" : "=l"(d) : "l"(a), "l"(b)); return d;
}

__device__ __forceinline__ void ld8(u64 (&r)[8], const float* p) {
    const ulonglong2* pp = reinterpret_cast<const ulonglong2*>(p);
    ulonglong2 a = pp[0], b = pp[1], c = pp[2], d = pp[3];
    r[0]=a.x; r[1]=a.y; r[2]=b.x; r[3]=b.y; r[4]=c.x; r[5]=c.y; r[6]=d.x; r[7]=d.y;
}

__device__ __forceinline__ float dot16u(const u64 (&qr)[8], const u64 (&k)[8]) {
    u64 d0 = mul2(qr[0],k[0]), d1 = mul2(qr[1],k[1]);
    u64 d2 = mul2(qr[2],k[2]), d3 = mul2(qr[3],k[3]);
    d0 = ffma2(qr[4],k[4],d0); d1 = ffma2(qr[5],k[5],d1);
    d2 = ffma2(qr[6],k[6],d2); d3 = ffma2(qr[7],k[7],d3);
    u64 e0 = add2(d0,d1), e1 = add2(d2,d3), e2 = add2(e0,e1);
    float lo, hi; unpack2(e2, lo, hi);
    return lo + hi;
}

__device__ __forceinline__ float dot4(u64 q0, u64 q1, u64 k0, u64 k1) {
    u64 d = mul2(q0,k0); d = ffma2(q1,k1,d);
    float lo, hi; unpack2(d, lo, hi);
    return lo + hi;
}

__device__ __forceinline__ void acc_fma_u(u64 (&acc)[8], u64 e2, const u64 (&v)[8]) {
    #pragma unroll
    for (int i = 0; i < 8; ++i) acc[i] = ffma2(e2, v[i], acc[i]);
}

template<int K>
__device__ __forceinline__ void topk_insert(float (&tv)[K], int (&ti)[K], float sc, int id) {
    bool done = false;
    #pragma unroll
    for (int i = K-1; i >= 1; --i) {
        if (!done) {
            if (sc > tv[i-1]) { tv[i] = tv[i-1]; ti[i] = ti[i-1]; }
            else              { tv[i] = sc; ti[i] = id; done = true; }
        }
    }
    if (!done) { tv[0] = sc; ti[0] = id; }
}

__device__ __forceinline__ void topk_insert_tie(float (&tv)[16], int (&ti)[16], float sc, int id) {
    bool done = false;
    #pragma unroll
    for (int i = 15; i >= 1; --i) {
        if (!done) {
            bool beats = (sc > tv[i-1]) || (sc == tv[i-1] && id < ti[i-1]);
            if (beats) { tv[i] = tv[i-1]; ti[i] = ti[i-1]; }
            else       { tv[i] = sc; ti[i] = id; done = true; }
        }
    }
    if (!done) { tv[0] = sc; ti[0] = id; }
}

// ---------------- transpose: NCHW [b,128,S] -> [b,h,S,16] ----------------
__global__ __launch_bounds__(256) void k_transpose(const float* __restrict__ in, int S, int which) {
    float* out = (which == 0) ? g_k1t : (which == 1) ? g_v1t : (which == 2) ? g_q1t :
                 (which == 3) ? g_k0t : (which == 4) ? g_v0t : (which == 5) ? g_q0t :
                 (which == 6) ? g_k2t : g_v2t;
    __shared__ float sm[128*17];
    const int b = blockIdx.z, h = blockIdx.y;
    const int s0 = blockIdx.x * 128;
    const int tid = threadIdx.x;
    const float* ib = in + ((size_t)(b*8 + h) * 16) * S + s0;
    #pragma unroll
    for (int k = 0; k < 8; ++k) {
        int lin = tid + k*256;
        int dd = lin >> 7, sl = lin & 127;
        sm[sl*17 + dd] = ib[dd*S + sl];
    }
    __syncthreads();
    float* ob = out + ((size_t)(b*8 + h) * S + s0) * 16;
    #pragma unroll
    for (int k = 0; k < 8; ++k) {
        int lin = tid + k*256;
        int sl = lin >> 4, dd = lin & 15;
        ob[lin] = sm[sl*17 + dd];
    }
}

// ---------------- level 0: full attention 32x32, warp-split x4, broadcast LDG ----------------
__global__ __launch_bounds__(128) void k_level0(const float* __restrict__ q2) {
    __shared__ float sZ[4][32];
    __shared__ float sAcc[4][32][16];
    __shared__ float sTv[4][32][16];
    __shared__ int   sTi[4][32][16];
    const int wid = threadIdx.x >> 5, lane = threadIdx.x & 31;
    const int bh = blockIdx.z * 8 + blockIdx.y;
    const int s = blockIdx.x * 32 + lane;

    const float* qb = q2 + (size_t)bh * 16 * 1024;
    u64 qr[8];
    #pragma unroll
    for (int i = 0; i < 8; ++i)
        qr[i] = pack2(qb[(2*i)*1024 + s], qb[(2*i+1)*1024 + s]);

    const float* kb = g_k2t + ((size_t)bh * 1024 + wid * 256) * 16;
    const float* vb = g_v2t + ((size_t)bh * 1024 + wid * 256) * 16;

    u64 acc[8];
    #pragma unroll
    for (int i = 0; i < 8; ++i) acc[i] = pack2(0.f, 0.f);
    float Z = 0.f;
    float topv[16]; int topi[16];
    #pragma unroll
    for (int i = 0; i < 16; ++i) { topv[i] = -1e30f; topi[i] = 0; }

    for (int j = 0; j < 256; ++j) {
        u64 k8[8]; ld8(k8, kb + (size_t)j*16);          // uniform addr -> 1 line
        float sc = dot16u(qr, k8) * 0.25f;
        u64 v8[8]; ld8(v8, vb + (size_t)j*16);
        if (sc > topv[15]) topk_insert<16>(topv, topi, sc, wid*256 + j);
        float e = __expf(sc);                            // no max-subtraction: |sc|<~6
        Z += e;
        acc_fma_u(acc, pack2(e, e), v8);
    }

    sZ[wid][lane] = Z;
    #pragma unroll
    for (int i = 0; i < 8; ++i) {
        float lo, hi; unpack2(acc[i], lo, hi);
        sAcc[wid][lane][2*i] = lo; sAcc[wid][lane][2*i+1] = hi;
    }
    #pragma unroll
    for (int r = 0; r < 16; ++r) { sTv[wid][lane][r] = topv[r]; sTi[wid][lane][r] = topi[r]; }
    __syncthreads();

    if (wid == 0) {
        float Zt = 0.f, af[16];
        #pragma unroll
        for (int ch = 0; ch < 16; ++ch) af[ch] = 0.f;
        #pragma unroll
        for (int tt = 0; tt < 4; ++tt) {
            Zt += sZ[tt][lane];
            #pragma unroll
            for (int ch = 0; ch < 16; ++ch) af[ch] += sAcc[tt][lane][ch];
        }
        float tv[16]; int ti[16];
        #pragma unroll
        for (int i = 0; i < 16; ++i) { tv[i] = -1e30f; ti[i] = 0x7fffffff; }
        for (int tt = 0; tt < 4; ++tt) {
            for (int r = 0; r < 16; ++r) {
                float v = sTv[tt][lane][r]; int id = sTi[tt][lane][r];
                bool beats = (v > tv[15]) || (v == tv[15] && id < ti[15]);
                if (beats) topk_insert_tie(tv, ti, v, id);
                else break;  // lists sorted desc (tie idx asc) -> monotone
            }
        }
        float inv = 1.f / Zt;
        float* mo = g_msg0 + ((size_t)bh*1024 + s)*16;
        #pragma unroll
        for (int ch = 0; ch < 16; ++ch) mo[ch] = af[ch] * inv;
        int* io = g_idx0 + ((size_t)bh*1024 + s)*16;
        #pragma unroll
        for (int r = 0; r < 16; ++r) io[r] = ti[r];
    }
}

// compare-exchange for desc sort, tie: slot asc
#define CE_(i,j) { bool sw_ = (lv[j] > lv[i]) || (lv[j] == lv[i] && ls[j] < ls[i]); \
    float a_ = sw_ ? lv[j] : lv[i]; float b_ = sw_ ? lv[i] : lv[j]; lv[i] = a_; lv[j] = b_; \
    int   c_ = sw_ ? ls[j] : ls[i]; int   d_ = sw_ ? ls[i] : ls[j]; ls[i] = c_; ls[j] = d_; }

// ---------------- level 1: warp per parent-list; lanes = (seg s in 4) x (cand c in 8) ----------------
__global__ __launch_bounds__(128) void k_level1() {
    const int wid = threadIdx.x >> 5, lane = threadIdx.x & 31;
    const int bh = blockIdx.z * 8 + blockIdx.y;
    const int l = blockIdx.x * 4 + wid;           // 0..1023
    const int s = lane & 3, c = lane >> 2;        // lane = c*4 + s
    const int ly = l >> 5, lx = l & 31;

    const float* qt = g_q1t + (size_t)bh * 4096 * 16;
    u64 q[4][2];
    #pragma unroll
    for (int t = 0; t < 4; ++t) {
        int s1 = (2*ly + (t>>1))*64 + 2*lx + (t&1);
        ulonglong2 v = *reinterpret_cast<const ulonglong2*>(qt + (size_t)s1*16 + s*4);
        q[t][0] = v.x; q[t][1] = v.y;
    }
    int myib = g_idx0[((size_t)bh*1024 + l)*16 + (lane & 15)];
    const float* kb = g_k1t + (size_t)bh * 4096 * 16;
    const float* vb = g_v1t + (size_t)bh * 4096 * 16;

    float Z[4] = {0.f, 0.f, 0.f, 0.f};
    u64 acc[4][2];
    #pragma unroll
    for (int t = 0; t < 4; ++t) { acc[t][0] = pack2(0.f,0.f); acc[t][1] = pack2(0.f,0.f); }
    float hist[8];

    #pragma unroll
    for (int j = 0; j < 8; ++j) {
        int p = __shfl_sync(0xffffffffu, myib, 2*j + (c>>2));   // parent of slot j*8+c
        int cand = (((p>>5)<<1) + ((c>>1)&1))*64 + ((p&31)<<1) + (c&1);
        ulonglong2 kk = *reinterpret_cast<const ulonglong2*>(kb + (size_t)cand*16 + s*4);
        ulonglong2 vv = *reinterpret_cast<const ulonglong2*>(vb + (size_t)cand*16 + s*4);
        float sc[4];
        #pragma unroll
        for (int t = 0; t < 4; ++t) {
            float ps = dot4(q[t][0], q[t][1], kk.x, kk.y);
            ps += __shfl_xor_sync(0xffffffffu, ps, 1);
            ps += __shfl_xor_sync(0xffffffffu, ps, 2);
            sc[t] = ps * 0.25f;
        }
        hist[j] = (s==0) ? sc[0] : (s==1) ? sc[1] : (s==2) ? sc[2] : sc[3];
        #pragma unroll
        for (int t = 0; t < 4; ++t) {
            float e = __expf(sc[t]);
            Z[t] += e;
            u64 e2 = pack2(e, e);
            acc[t][0] = ffma2(e2, vv.x, acc[t][0]);
            acc[t][1] = ffma2(e2, vv.y, acc[t][1]);
        }
    }
    // merge over candidate lanes (xor 4, 8, 16)
    #pragma unroll
    for (int t = 0; t < 4; ++t) {
        Z[t] += __shfl_xor_sync(0xffffffffu, Z[t], 4);
        Z[t] += __shfl_xor_sync(0xffffffffu, Z[t], 8);
        Z[t] += __shfl_xor_sync(0xffffffffu, Z[t], 16);
        #pragma unroll
        for (int u = 0; u < 2; ++u) {
            acc[t][u] = add2(acc[t][u], __shfl_xor_sync(0xffffffffu, acc[t][u], 4));
            acc[t][u] = add2(acc[t][u], __shfl_xor_sync(0xffffffffu, acc[t][u], 8));
            acc[t][u] = add2(acc[t][u], __shfl_xor_sync(0xffffffffu, acc[t][u], 16));
        }
    }

    // ---- top-8 per query t=s, done by the 8 lanes sharing s (xor 4,8,16) ----
    float lv[9]; int ls[9];
    #pragma unroll
    for (int j = 0; j < 8; ++j) { lv[j] = hist[j]; ls[j] = j*8 + c; }
    lv[8] = -1e30f; ls[8] = 0x7fffffff;
    CE_(0,1) CE_(2,3) CE_(4,5) CE_(6,7)
    CE_(0,2) CE_(1,3) CE_(4,6) CE_(5,7)
    CE_(1,2) CE_(5,6)
    CE_(0,4) CE_(1,5) CE_(2,6) CE_(3,7)
    CE_(2,4) CE_(3,5)
    CE_(1,2) CE_(3,4) CE_(5,6)
    int wc[8];
    #pragma unroll
    for (int r = 0; r < 8; ++r) {
        float v = lv[0]; int sl = ls[0];
        {
            float ov = __shfl_xor_sync(0xffffffffu, v, 4);
            int   os = __shfl_xor_sync(0xffffffffu, sl, 4);
            if (ov > v || (ov == v && os < sl)) { v = ov; sl = os; }
            ov = __shfl_xor_sync(0xffffffffu, v, 8);
            os = __shfl_xor_sync(0xffffffffu, sl, 8);
            if (ov > v || (ov == v && os < sl)) { v = ov; sl = os; }
            ov = __shfl_xor_sync(0xffffffffu, v, 16);
            os = __shfl_xor_sync(0xffffffffu, sl, 16);
            if (ov > v || (ov == v && os < sl)) { v = ov; sl = os; }
        }
        int p = __shfl_sync(0xffffffffu, myib, sl >> 2);
        int ch2 = sl & 3;
        wc[r] = (((p>>5)<<1) + (ch2>>1))*64 + ((p&31)<<1) + (ch2&1);
        bool own = ((sl & 7) == c);
        #pragma unroll
        for (int i = 0; i < 8; ++i) {
            lv[i] = own ? lv[i+1] : lv[i];
            ls[i] = own ? ls[i+1] : ls[i];
        }
    }

    if (c == 0) {
        #pragma unroll
        for (int t = 0; t < 4; ++t) {
            float inv = 1.f / Z[t];
            u64 i2 = pack2(inv, inv);
            ulonglong2 o; o.x = mul2(acc[t][0], i2); o.y = mul2(acc[t][1], i2);
            *reinterpret_cast<ulonglong2*>(g_msg1 + (((size_t)bh*1024 + l)*4 + t)*16 + s*4) = o;
        }
        int t = s;
        int s1 = (2*ly + (t>>1))*64 + 2*lx + (t&1);
        int* io = g_idx1 + ((size_t)bh*4096 + s1)*8;
        #pragma unroll
        for (int r = 0; r < 8; ++r) io[r] = wc[r];
    }
}

// ---------------- level 2: warp per 2 lists; lanes = (pair h) x (seg s in 4) x (cand c in 4) ----------------
__global__ __launch_bounds__(128) void k_level2() {
    const int wid = threadIdx.x >> 5, lane = threadIdx.x & 31;
    const int bh = blockIdx.z * 8 + blockIdx.y;
    const int lp = blockIdx.x * 4 + wid;           // 0..2047
    const int h = lane >> 4, within = lane & 15;
    const int s = within & 3, c = within >> 2;     // c in 0..3
    const int l = lp*2 + h;                        // level-1 pixel 0..4095
    const int ly = l >> 6, lx = l & 63;

    const float* qt = g_q0t + (size_t)bh * 16384 * 16;
    u64 q[4][2];
    #pragma unroll
    for (int t = 0; t < 4; ++t) {
        int s0 = (2*ly + (t>>1))*128 + 2*lx + (t&1);
        ulonglong2 v = *reinterpret_cast<const ulonglong2*>(qt + (size_t)s0*16 + s*4);
        q[t][0] = v.x; q[t][1] = v.y;
    }
    int myib = (within < 8) ? g_idx1[((size_t)bh*4096 + l)*8 + within] : 0;
    const float* kb = g_k0t + (size_t)bh * 16384 * 16;
    const float* vb = g_v0t + (size_t)bh * 16384 * 16;

    float Z[4] = {0.f, 0.f, 0.f, 0.f};
    u64 acc[4][2];
    #pragma unroll
    for (int t = 0; t < 4; ++t) { acc[t][0] = pack2(0.f,0.f); acc[t][1] = pack2(0.f,0.f); }

    #pragma unroll
    for (int j = 0; j < 8; ++j) {
        int p = __shfl_sync(0xffffffffu, myib, h*16 + j);   // parent j of this half's list
        int cand = (((p>>6)<<1) + ((c>>1)&1))*128 + ((p&63)<<1) + (c&1);
        ulonglong2 kk = *reinterpret_cast<const ulonglong2*>(kb + (size_t)cand*16 + s*4);
        ulonglong2 vv = *reinterpret_cast<const ulonglong2*>(vb + (size_t)cand*16 + s*4);
        float sc[4];
        #pragma unroll
        for (int t = 0; t < 4; ++t) {
            float ps = dot4(q[t][0], q[t][1], kk.x, kk.y);
            ps += __shfl_xor_sync(0xffffffffu, ps, 1);
            ps += __shfl_xor_sync(0xffffffffu, ps, 2);
            sc[t] = ps * 0.25f;
        }
        #pragma unroll
        for (int t = 0; t < 4; ++t) {
            float e = __expf(sc[t]);
            Z[t] += e;
            u64 e2 = pack2(e, e);
            acc[t][0] = ffma2(e2, vv.x, acc[t][0]);
            acc[t][1] = ffma2(e2, vv.y, acc[t][1]);
        }
    }
    // merge over candidate lanes (xor 4, 8) — stays within half
    #pragma unroll
    for (int t = 0; t < 4; ++t) {
        Z[t] += __shfl_xor_sync(0xffffffffu, Z[t], 4);
        Z[t] += __shfl_xor_sync(0xffffffffu, Z[t], 8);
        #pragma unroll
        for (int u = 0; u < 2; ++u) {
            acc[t][u] = add2(acc[t][u], __shfl_xor_sync(0xffffffffu, acc[t][u], 4));
            acc[t][u] = add2(acc[t][u], __shfl_xor_sync(0xffffffffu, acc[t][u], 8));
        }
    }
    if (c == 0) {
        #pragma unroll
        for (int t = 0; t < 4; ++t) {
            float inv = 1.f / Z[t];
            u64 i2 = pack2(inv, inv);
            ulonglong2 o; o.x = mul2(acc[t][0], i2); o.y = mul2(acc[t][1], i2);
            *reinterpret_cast<ulonglong2*>(g_msg2 + (((size_t)bh*4096 + l)*4 + t)*16 + s*4) = o;
        }
    }
}

// ---------------- combine: weighted pyramid sum ----------------
__global__ __launch_bounds__(256) void k_combine(const float* __restrict__ wt, float* __restrict__ out) {
    const int gid = blockIdx.x * 256 + threadIdx.x;
    float w0r = wt[0], w1r = wt[1], w2r = wt[2];
    float mx = fmaxf(w0r, fmaxf(w1r, w2r));
    float e0 = expf(w0r - mx), e1 = expf(w1r - mx), e2 = expf(w2r - mx);
    float inv = 1.f / (e0 + e1 + e2);
    float w0 = e0*inv, w1 = e1*inv, w2 = e2*inv;

    const int h = gid & 7;
    const int s = (gid >> 3) & 16383;
    const int b = gid >> 17;
    const int y = s >> 7, x = s & 127;
    const int bh = b*8 + h;
    const int l0 = (y >> 2)*32 + (x >> 2);
    const int t1 = (((y >> 1) & 1) << 1) | ((x >> 1) & 1);
    const int l2 = (y >> 1)*64 + (x >> 1);
    const int t2 = ((y & 1) << 1) | (x & 1);

    const float4* p0 = reinterpret_cast<const float4*>(g_msg0 + (size_t)(bh*1024 + l0)*16);
    const float4* p1 = reinterpret_cast<const float4*>(g_msg1 + (size_t)((bh*1024 + l0)*4 + t1)*16);
    const float4* p2 = reinterpret_cast<const float4*>(g_msg2 + (size_t)((bh*4096 + l2)*4 + t2)*16);
    float4* po = reinterpret_cast<float4*>(out + (size_t)gid*16);
    #pragma unroll
    for (int i = 0; i < 4; ++i) {
        float4 a = p0[i], c = p1[i], d = p2[i];
        float4 r;
        r.x = w0*a.x + w1*c.x + w2*d.x;
        r.y = w0*a.y + w1*c.y + w2*d.y;
        r.z = w0*a.z + w1*c.z + w2*d.z;
        r.w = w0*a.w + w1*c.w + w2*d.w;
        po[i] = r;
    }
}

// ---------------- launcher ----------------
extern "C" void kernel_launch(void* const* d_in, const int* in_sizes, int n_in,
                              void* d_out, int out_size) {
    (void)in_sizes; (void)n_in; (void)out_size;
    const float* q0 = (const float*)d_in[0];
    const float* q1 = (const float*)d_in[1];
    const float* q2 = (const float*)d_in[2];
    const float* k0 = (const float*)d_in[3];
    const float* k1 = (const float*)d_in[4];
    const float* k2 = (const float*)d_in[5];
    const float* v0 = (const float*)d_in[6];
    const float* v1 = (const float*)d_in[7];
    const float* v2 = (const float*)d_in[8];
    const float* wt = (const float*)d_in[9];
    float* out = (float*)d_out;

    k_transpose<<<dim3(8,   8, 4), 256>>>(k2, 1024, 6);
    k_transpose<<<dim3(8,   8, 4), 256>>>(v2, 1024, 7);
    k_transpose<<<dim3(32,  8, 4), 256>>>(k1, 4096, 0);
    k_transpose<<<dim3(32,  8, 4), 256>>>(v1, 4096, 1);
    k_transpose<<<dim3(32,  8, 4), 256>>>(q1, 4096, 2);
    k_transpose<<<dim3(128, 8, 4), 256>>>(k0, 16384, 3);
    k_transpose<<<dim3(128, 8, 4), 256>>>(v0, 16384, 4);
    k_transpose<<<dim3(128, 8, 4), 256>>>(q0, 16384, 5);
    k_level0<<<dim3(32,  8, 4), 128>>>(q2);
    k_level1<<<dim3(256, 8, 4), 128>>>();
    k_level2<<<dim3(512, 8, 4), 128>>>();
    k_combine<<<2048, 256>>>(wt, out);
}

// round 13
// speedup vs baseline: 1.4397x; 1.4397x over previous
#include <cuda_runtime.h>

typedef unsigned long long u64;

// ---------------- scratch (static device globals: allocation-free) ----------------
__device__ __align__(128) float g_k1t[4*8*4096*16];    // [b,h,s,d]
__device__ __align__(128) float g_v1t[4*8*4096*16];
__device__ __align__(128) float g_q1t[4*8*4096*16];
__device__ __align__(128) float g_k0t[4*8*16384*16];
__device__ __align__(128) float g_v0t[4*8*16384*16];
__device__ __align__(128) float g_q0t[4*8*16384*16];
__device__ __align__(128) float g_k2t[4*8*1024*16];
__device__ __align__(128) float g_v2t[4*8*1024*16];
__device__ __align__(128) float g_msg0[4*8*1024*16];       // [b,h,l,d]
__device__ __align__(128) float g_msg1[4*8*1024*4*16];     // [b,h,l,t,d]
__device__ __align__(128) float g_msg2[4*8*4096*4*16];     // [b,h,l,t,d]
__device__ int   g_idx0[4*8*1024*16];          // [b,h,l,16]
__device__ int   g_idx1[4*8*4096*8];           // [b,h,pix,8]

// ---------------- packed f32x2 helpers ----------------
__device__ __forceinline__ u64 pack2(float a, float b) {
    u64 r; asm("mov.b64 %0,{%1,%2};" : "=l"(r) : "f"(a), "f"(b)); return r;
}
__device__ __forceinline__ void unpack2(u64 v, float& a, float& b) {
    asm("mov.b64 {%0,%1},%2;" : "=f"(a), "=f"(b) : "l"(v));
}
__device__ __forceinline__ u64 ffma2(u64 a, u64 b, u64 c) {
    u64 d; asm("fma.rn.f32x2 %0,%1,%2,%3;" : "=l"(d) : "l"(a), "l"(b), "l"(c)); return d;
}
__device__ __forceinline__ u64 mul2(u64 a, u64 b) {
    u64 d; asm("mul.rn.f32x2 %0,%1,%2;" : "=l"(d) : "l"(a), "l"(b)); return d;
}
__device__ __forceinline__ u64 add2(u64 a, u64 b) {
    u64 d; asm("add.rn.f32x2 %0,%1,%2;" : "=l"(d) : "l"(a), "l"(b)); return d;
}

__device__ __forceinline__ void ld8(u64 (&r)[8], const float* p) {
    const ulonglong2* pp = reinterpret_cast<const ulonglong2*>(p);
    ulonglong2 a = pp[0], b = pp[1], c = pp[2], d = pp[3];
    r[0]=a.x; r[1]=a.y; r[2]=b.x; r[3]=b.y; r[4]=c.x; r[5]=c.y; r[6]=d.x; r[7]=d.y;
}

__device__ __forceinline__ float dot16u(const u64 (&qr)[8], const u64 (&k)[8]) {
    u64 d0 = mul2(qr[0],k[0]), d1 = mul2(qr[1],k[1]);
    u64 d2 = mul2(qr[2],k[2]), d3 = mul2(qr[3],k[3]);
    d0 = ffma2(qr[4],k[4],d0); d1 = ffma2(qr[5],k[5],d1);
    d2 = ffma2(qr[6],k[6],d2); d3 = ffma2(qr[7],k[7],d3);
    u64 e0 = add2(d0,d1), e1 = add2(d2,d3), e2 = add2(e0,e1);
    float lo, hi; unpack2(e2, lo, hi);
    return lo + hi;
}

__device__ __forceinline__ void acc_fma_u(u64 (&acc)[8], u64 e2, const u64 (&v)[8]) {
    #pragma unroll
    for (int i = 0; i < 8; ++i) acc[i] = ffma2(e2, v[i], acc[i]);
}

template<int K>
__device__ __forceinline__ void topk_insert(float (&tv)[K], int (&ti)[K], float sc, int id) {
    bool done = false;
    #pragma unroll
    for (int i = K-1; i >= 1; --i) {
        if (!done) {
            if (sc > tv[i-1]) { tv[i] = tv[i-1]; ti[i] = ti[i-1]; }
            else              { tv[i] = sc; ti[i] = id; done = true; }
        }
    }
    if (!done) { tv[0] = sc; ti[0] = id; }
}

__device__ __forceinline__ void topk_insert_tie(float (&tv)[16], int (&ti)[16], float sc, int id) {
    bool done = false;
    #pragma unroll
    for (int i = 15; i >= 1; --i) {
        if (!done) {
            bool beats = (sc > tv[i-1]) || (sc == tv[i-1] && id < ti[i-1]);
            if (beats) { tv[i] = tv[i-1]; ti[i] = ti[i-1]; }
            else       { tv[i] = sc; ti[i] = id; done = true; }
        }
    }
    if (!done) { tv[0] = sc; ti[0] = id; }
}

// ---------------- fused vectorized transpose: NCHW [b,128,S] -> [b,h,S,16] ----------------
// smem row stride 132 floats = 528 B (multiple of 16: float4-safe; 132 % 32 banks = 4)
__global__ __launch_bounds__(256) void k_transpose_all(
    const float* __restrict__ q0, const float* __restrict__ q1,
    const float* __restrict__ k0, const float* __restrict__ k1,
    const float* __restrict__ k2, const float* __restrict__ v0,
    const float* __restrict__ v1, const float* __restrict__ v2) {
    __shared__ __align__(16) float sm[16*132];
    int bid = blockIdx.x;
    const float* in; float* out; int S, lg2, local;
    if (bid < 256)        { in=k2; out=g_k2t; S=1024;  lg2=3; local=bid; }
    else if (bid < 512)   { in=v2; out=g_v2t; S=1024;  lg2=3; local=bid-256; }
    else if (bid < 1536)  { in=k1; out=g_k1t; S=4096;  lg2=5; local=bid-512; }
    else if (bid < 2560)  { in=v1; out=g_v1t; S=4096;  lg2=5; local=bid-1536; }
    else if (bid < 3584)  { in=q1; out=g_q1t; S=4096;  lg2=5; local=bid-2560; }
    else if (bid < 7680)  { in=k0; out=g_k0t; S=16384; lg2=7; local=bid-3584; }
    else if (bid < 11776) { in=v0; out=g_v0t; S=16384; lg2=7; local=bid-7680; }
    else                  { in=q0; out=g_q0t; S=16384; lg2=7; local=bid-11776; }
    const int bh = local >> lg2;
    const int s0 = (local & ((1 << lg2) - 1)) << 7;
    const int tid = threadIdx.x;
    const float* ib = in + ((size_t)bh * 16) * S + s0;
    #pragma unroll
    for (int k = 0; k < 2; ++k) {
        int fid = tid + k*256;               // 0..511
        int dd = fid >> 5, c4 = fid & 31;
        float4 v = *reinterpret_cast<const float4*>(ib + (size_t)dd*S + c4*4);
        *reinterpret_cast<float4*>(sm + dd*132 + c4*4) = v;
    }
    __syncthreads();
    float* ob = out + ((size_t)bh * S + s0) * 16;
    #pragma unroll
    for (int k = 0; k < 2; ++k) {
        int w = tid + k*256;
        int sl = w >> 2, d0 = (w & 3) << 2;
        float4 v;
        v.x = sm[(d0+0)*132 + sl];
        v.y = sm[(d0+1)*132 + sl];
        v.z = sm[(d0+2)*132 + sl];
        v.w = sm[(d0+3)*132 + sl];
        *reinterpret_cast<float4*>(ob + sl*16 + d0) = v;
    }
}

// ---------------- dummy (profiling alignment) ----------------
__global__ void k_dummy() {}

// ---------------- level 0: full attention 32x32, warp-split x4, broadcast LDG ----------------
__global__ __launch_bounds__(128) void k_level0(const float* __restrict__ q2) {
    __shared__ float sZ[4][32];
    __shared__ float sAcc[4][32][16];
    __shared__ float sTv[4][32][16];
    __shared__ int   sTi[4][32][16];
    const int wid = threadIdx.x >> 5, lane = threadIdx.x & 31;
    const int bh = blockIdx.z * 8 + blockIdx.y;
    const int s = blockIdx.x * 32 + lane;

    const float* qb = q2 + (size_t)bh * 16 * 1024;
    u64 qr[8];
    #pragma unroll
    for (int i = 0; i < 8; ++i)
        qr[i] = pack2(qb[(2*i)*1024 + s], qb[(2*i+1)*1024 + s]);

    const float* kb = g_k2t + ((size_t)bh * 1024 + wid * 256) * 16;
    const float* vb = g_v2t + ((size_t)bh * 1024 + wid * 256) * 16;

    u64 acc[8];
    #pragma unroll
    for (int i = 0; i < 8; ++i) acc[i] = pack2(0.f, 0.f);
    float Z = 0.f;
    float topv[16]; int topi[16];
    #pragma unroll
    for (int i = 0; i < 16; ++i) { topv[i] = -1e30f; topi[i] = 0; }

    for (int j = 0; j < 256; ++j) {
        u64 k8[8]; ld8(k8, kb + (size_t)j*16);          // uniform addr -> 1 line
        float sc = dot16u(qr, k8) * 0.25f;
        u64 v8[8]; ld8(v8, vb + (size_t)j*16);
        if (sc > topv[15]) topk_insert<16>(topv, topi, sc, wid*256 + j);
        float e = __expf(sc);                            // |sc| small: no max-sub
        Z += e;
        acc_fma_u(acc, pack2(e, e), v8);
    }

    sZ[wid][lane] = Z;
    #pragma unroll
    for (int i = 0; i < 8; ++i) {
        float lo, hi; unpack2(acc[i], lo, hi);
        sAcc[wid][lane][2*i] = lo; sAcc[wid][lane][2*i+1] = hi;
    }
    #pragma unroll
    for (int r = 0; r < 16; ++r) { sTv[wid][lane][r] = topv[r]; sTi[wid][lane][r] = topi[r]; }
    __syncthreads();

    if (wid == 0) {
        float Zt = 0.f, af[16];
        #pragma unroll
        for (int ch = 0; ch < 16; ++ch) af[ch] = 0.f;
        #pragma unroll
        for (int tt = 0; tt < 4; ++tt) {
            Zt += sZ[tt][lane];
            #pragma unroll
            for (int ch = 0; ch < 16; ++ch) af[ch] += sAcc[tt][lane][ch];
        }
        float tv[16]; int ti[16];
        #pragma unroll
        for (int i = 0; i < 16; ++i) { tv[i] = -1e30f; ti[i] = 0x7fffffff; }
        for (int tt = 0; tt < 4; ++tt) {
            for (int r = 0; r < 16; ++r) {
                float v = sTv[tt][lane][r]; int id = sTi[tt][lane][r];
                bool beats = (v > tv[15]) || (v == tv[15] && id < ti[15]);
                if (beats) topk_insert_tie(tv, ti, v, id);
                else break;  // lists sorted desc (tie idx asc) -> monotone
            }
        }
        float inv = 1.f / Zt;
        float* mo = g_msg0 + ((size_t)bh*1024 + s)*16;
        #pragma unroll
        for (int ch = 0; ch < 16; ++ch) mo[ch] = af[ch] * inv;
        int* io = g_idx0 + ((size_t)bh*1024 + s)*16;
        #pragma unroll
        for (int r = 0; r < 16; ++r) io[r] = ti[r];
    }
}

// ============= level 1: smem-staged gather, 32 lists/block, 16 parent-chunks =============
// Chunk buffer layout: rows r = c*32 + list_local (128 rows of 16 floats, stride 20)
__global__ __launch_bounds__(128) void k_level1() {
    __shared__ int sPar[32][16];
    __shared__ __align__(16) float sK[2][128*20];
    __shared__ __align__(16) float sV[2][128*20];
    const int tid = threadIdx.x;
    const int bh = blockIdx.z * 8 + blockIdx.y;
    const int lbase = blockIdx.x * 32;
    const int lg = tid >> 2, t = tid & 3;
    const int l = lbase + lg;

    // parents: 32 lists x 16
    #pragma unroll
    for (int k = 0; k < 4; ++k) {
        int id = tid + k*128;
        (&sPar[0][0])[id] = g_idx0[((size_t)bh*1024 + lbase + (id >> 4))*16 + (id & 15)];
    }

    const int ly = l >> 5, lx = l & 31;
    const int s1 = (2*ly + (t >> 1))*64 + 2*lx + (t & 1);
    u64 qr[8]; ld8(qr, g_q1t + ((size_t)bh*4096 + s1)*16);

    const float* kb = g_k1t + (size_t)bh * 4096 * 16;
    const float* vb = g_v1t + (size_t)bh * 4096 * 16;

    u64 acc[8];
    #pragma unroll
    for (int i = 0; i < 8; ++i) acc[i] = pack2(0.f, 0.f);
    float Z = 0.f;
    float topv[8]; int topi[8];
    #pragma unroll
    for (int i = 0; i < 8; ++i) { topv[i] = -1e30f; topi[i] = 0; }

    __syncthreads();   // parents visible

    // stage chunk 0
    #pragma unroll
    for (int k = 0; k < 8; ++k) {
        int sid = tid + k*128;
        int row = sid >> 2, sseg = sid & 3;
        int r = row & 127;
        int c = r >> 5, lst = r & 31;
        int p = sPar[lst][0];
        int cand = (((p >> 5) << 1) + (c >> 1))*64 + ((p & 31) << 1) + (c & 1);
        const float* src = (row < 128 ? kb : vb) + ((size_t)cand*16 + sseg*4);
        float* dst = (row < 128 ? sK[0] : sV[0]) + r*20 + sseg*4;
        *reinterpret_cast<float4*>(dst) = *reinterpret_cast<const float4*>(src);
    }

    for (int w = 0; w < 16; ++w) {
        __syncthreads();
        int buf = w & 1;
        if (w + 1 < 16) {
            int nb = (w + 1) & 1;
            #pragma unroll
            for (int k = 0; k < 8; ++k) {
                int sid = tid + k*128;
                int row = sid >> 2, sseg = sid & 3;
                int r = row & 127;
                int c = r >> 5, lst = r & 31;
                int p = sPar[lst][w + 1];
                int cand = (((p >> 5) << 1) + (c >> 1))*64 + ((p & 31) << 1) + (c & 1);
                const float* src = (row < 128 ? kb : vb) + ((size_t)cand*16 + sseg*4);
                float* dst = (row < 128 ? sK[nb] : sV[nb]) + r*20 + sseg*4;
                *reinterpret_cast<float4*>(dst) = *reinterpret_cast<const float4*>(src);
            }
        }
        #pragma unroll
        for (int c = 0; c < 4; ++c) {
            int r = c*32 + lg;
            u64 k8[8]; ld8(k8, sK[buf] + r*20);
            float sc = dot16u(qr, k8) * 0.25f;
            u64 v8[8]; ld8(v8, sV[buf] + r*20);
            if (sc > topv[7]) topk_insert<8>(topv, topi, sc, w*4 + c);
            float e = __expf(sc);
            Z += e;
            acc_fma_u(acc, pack2(e, e), v8);
        }
    }

    // finalize
    float inv = 1.f / Z;
    u64 i2 = pack2(inv, inv);
    float* mo = g_msg1 + (((size_t)bh*1024 + l)*4 + t)*16;
    #pragma unroll
    for (int i = 0; i < 8; ++i) {
        float lo, hi; unpack2(mul2(acc[i], i2), lo, hi);
        mo[2*i] = lo; mo[2*i+1] = hi;
    }
    int* io = g_idx1 + ((size_t)bh*4096 + s1)*8;
    #pragma unroll
    for (int r = 0; r < 8; ++r) {
        int slot = topi[r];
        int p = sPar[lg][slot >> 2];
        int c = slot & 3;
        io[r] = (((p >> 5) << 1) + (c >> 1))*64 + ((p & 31) << 1) + (c & 1);
    }
}

// ============= level 2: smem-staged gather, 32 lists/block, 8 parent-chunks =============
__global__ __launch_bounds__(128) void k_level2() {
    __shared__ int sPar[32][8];
    __shared__ __align__(16) float sK[2][128*20];
    __shared__ __align__(16) float sV[2][128*20];
    const int tid = threadIdx.x;
    const int bh = blockIdx.z * 8 + blockIdx.y;
    const int lbase = blockIdx.x * 32;
    const int lg = tid >> 2, t = tid & 3;
    const int l = lbase + lg;

    #pragma unroll
    for (int k = 0; k < 2; ++k) {
        int id = tid + k*128;
        (&sPar[0][0])[id] = g_idx1[((size_t)bh*4096 + lbase + (id >> 3))*8 + (id & 7)];
    }

    const int ly = l >> 6, lx = l & 63;
    const int s0 = (2*ly + (t >> 1))*128 + 2*lx + (t & 1);
    u64 qr[8]; ld8(qr, g_q0t + ((size_t)bh*16384 + s0)*16);

    const float* kb = g_k0t + (size_t)bh * 16384 * 16;
    const float* vb = g_v0t + (size_t)bh * 16384 * 16;

    u64 acc[8];
    #pragma unroll
    for (int i = 0; i < 8; ++i) acc[i] = pack2(0.f, 0.f);
    float Z = 0.f;

    __syncthreads();

    #pragma unroll
    for (int k = 0; k < 8; ++k) {
        int sid = tid + k*128;
        int row = sid >> 2, sseg = sid & 3;
        int r = row & 127;
        int c = r >> 5, lst = r & 31;
        int p = sPar[lst][0];
        int cand = (((p >> 6) << 1) + (c >> 1))*128 + ((p & 63) << 1) + (c & 1);
        const float* src = (row < 128 ? kb : vb) + ((size_t)cand*16 + sseg*4);
        float* dst = (row < 128 ? sK[0] : sV[0]) + r*20 + sseg*4;
        *reinterpret_cast<float4*>(dst) = *reinterpret_cast<const float4*>(src);
    }

    for (int w = 0; w < 8; ++w) {
        __syncthreads();
        int buf = w & 1;
        if (w + 1 < 8) {
            int nb = (w + 1) & 1;
            #pragma unroll
            for (int k = 0; k < 8; ++k) {
                int sid = tid + k*128;
                int row = sid >> 2, sseg = sid & 3;
                int r = row & 127;
                int c = r >> 5, lst = r & 31;
                int p = sPar[lst][w + 1];
                int cand = (((p >> 6) << 1) + (c >> 1))*128 + ((p & 63) << 1) + (c & 1);
                const float* src = (row < 128 ? kb : vb) + ((size_t)cand*16 + sseg*4);
                float* dst = (row < 128 ? sK[nb] : sV[nb]) + r*20 + sseg*4;
                *reinterpret_cast<float4*>(dst) = *reinterpret_cast<const float4*>(src);
            }
        }
        #pragma unroll
        for (int c = 0; c < 4; ++c) {
            int r = c*32 + lg;
            u64 k8[8]; ld8(k8, sK[buf] + r*20);
            float sc = dot16u(qr, k8) * 0.25f;
            u64 v8[8]; ld8(v8, sV[buf] + r*20);
            float e = __expf(sc);
            Z += e;
            acc_fma_u(acc, pack2(e, e), v8);
        }
    }

    float inv = 1.f / Z;
    u64 i2 = pack2(inv, inv);
    float* mo = g_msg2 + (((size_t)bh*4096 + l)*4 + t)*16;
    #pragma unroll
    for (int i = 0; i < 8; ++i) {
        float lo, hi; unpack2(mul2(acc[i], i2), lo, hi);
        mo[2*i] = lo; mo[2*i+1] = hi;
    }
}

// ---------------- combine: weighted pyramid sum ----------------
__global__ __launch_bounds__(256) void k_combine(const float* __restrict__ wt, float* __restrict__ out) {
    const int gid = blockIdx.x * 256 + threadIdx.x;
    float w0r = wt[0], w1r = wt[1], w2r = wt[2];
    float mx = fmaxf(w0r, fmaxf(w1r, w2r));
    float e0 = expf(w0r - mx), e1 = expf(w1r - mx), e2 = expf(w2r - mx);
    float inv = 1.f / (e0 + e1 + e2);
    float w0 = e0*inv, w1 = e1*inv, w2 = e2*inv;

    const int h = gid & 7;
    const int s = (gid >> 3) & 16383;
    const int b = gid >> 17;
    const int y = s >> 7, x = s & 127;
    const int bh = b*8 + h;
    const int l0 = (y >> 2)*32 + (x >> 2);
    const int t1 = (((y >> 1) & 1) << 1) | ((x >> 1) & 1);
    const int l2 = (y >> 1)*64 + (x >> 1);
    const int t2 = ((y & 1) << 1) | (x & 1);

    const float4* p0 = reinterpret_cast<const float4*>(g_msg0 + (size_t)(bh*1024 + l0)*16);
    const float4* p1 = reinterpret_cast<const float4*>(g_msg1 + (size_t)((bh*1024 + l0)*4 + t1)*16);
    const float4* p2 = reinterpret_cast<const float4*>(g_msg2 + (size_t)((bh*4096 + l2)*4 + t2)*16);
    float4* po = reinterpret_cast<float4*>(out + (size_t)gid*16);
    #pragma unroll
    for (int i = 0; i < 4; ++i) {
        float4 a = p0[i], c = p1[i], d = p2[i];
        float4 r;
        r.x = w0*a.x + w1*c.x + w2*d.x;
        r.y = w0*a.y + w1*c.y + w2*d.y;
        r.z = w0*a.z + w1*c.z + w2*d.z;
        r.w = w0*a.w + w1*c.w + w2*d.w;
        po[i] = r;
    }
}

// ---------------- launcher ----------------
extern "C" void kernel_launch(void* const* d_in, const int* in_sizes, int n_in,
                              void* d_out, int out_size) {
    (void)in_sizes; (void)n_in; (void)out_size;
    const float* q0 = (const float*)d_in[0];
    const float* q1 = (const float*)d_in[1];
    const float* q2 = (const float*)d_in[2];
    const float* k0 = (const float*)d_in[3];
    const float* k1 = (const float*)d_in[4];
    const float* k2 = (const float*)d_in[5];
    const float* v0 = (const float*)d_in[6];
    const float* v1 = (const float*)d_in[7];
    const float* v2 = (const float*)d_in[8];
    const float* wt = (const float*)d_in[9];
    float* out = (float*)d_out;

    k_transpose_all<<<15872, 256>>>(q0, q1, k0, k1, k2, v0, v1, v2);
    k_dummy<<<1, 32>>>();                           // align ncu capture onto k_level0
    k_level0<<<dim3(32,  8, 4), 128>>>(q2);
    k_level1<<<dim3(32,  8, 4), 128>>>();
    k_level2<<<dim3(128, 8, 4), 128>>>();
    k_combine<<<2048, 256>>>(wt, out);
}